// round 1
// baseline (speedup 1.0000x reference)
#include <cuda_runtime.h>

#define B_  64
#define P_  2048
#define D_  1024
#define TILE_P 256
#define TILE_K 16
#define NTILES (P_ / TILE_P)   /* 8 p-tiles */
#define RA 260                 /* As row pitch (floats), 16B-aligned rows */
#define RB 68                  /* Bs row pitch (floats), 16B-aligned rows */

// Scratch: per (b, ptile) partial max over the 256 p rows, for each of 64 sentences.
__device__ float g_partial[B_ * NTILES * B_];

__device__ __forceinline__ unsigned long long pack2(float x, float y) {
    unsigned long long r;
    asm("mov.b64 %0, {%1, %2};" : "=l"(r) : "f"(x), "f"(y));
    return r;
}
__device__ __forceinline__ void unpack2(unsigned long long v, float &x, float &y) {
    asm("mov.b64 {%0, %1}, %2;" : "=f"(x), "=f"(y) : "l"(v));
}
// Packed dual-FMA: acc.{lo,hi} += a.{lo,hi} * b.{lo,hi}   (Blackwell f32x2 pipe)
__device__ __forceinline__ void fma2(unsigned long long &acc, unsigned long long a,
                                     unsigned long long b) {
    asm("fma.rn.f32x2 %0, %1, %2, %0;" : "+l"(acc) : "l"(a), "l"(b));
}

// Grid: (NTILES, B_). Each CTA: sim tile [256 p x 64 c] for one video b,
// then max over its 256 p rows -> g_partial[b][ptile][c].
__global__ __launch_bounds__(256, 2)
void gemm_max_kernel(const float* __restrict__ im, const float* __restrict__ dis) {
    __shared__ float As[TILE_K][RA];
    __shared__ float Bs[TILE_K][RB];
    __shared__ float red[32][B_];

    const int tid = threadIdx.x;
    const int b  = blockIdx.y;
    const int pt = blockIdx.x;
    const int tx = tid & 7;    // c group: 8 columns each
    const int ty = tid >> 3;   // p group: 8 rows each

    // Per-thread gmem rows: thread owns p row = tid of this tile (A), and one
    // (c, k-quarter) slot of the B tile.
    const float* aRow = im + ((size_t)b * P_ + (size_t)pt * TILE_P + tid) * D_;
    const float* bRow = dis + (size_t)(tid & 63) * D_ + (size_t)((tid >> 6) * 4);

    // Prefetch first k-tile into registers.
    float4 pa[4], pb;
    #pragma unroll
    for (int it = 0; it < 4; ++it) pa[it] = *(const float4*)(aRow + it * 4);
    pb = *(const float4*)(bRow);

    unsigned long long acc[4][8];  // [p-pair][c], packed f32x2 along p
    #pragma unroll
    for (int i = 0; i < 4; ++i)
        #pragma unroll
        for (int j = 0; j < 8; ++j) acc[i][j] = 0ull;

    for (int kt = 0; kt < D_; kt += TILE_K) {
        // Stage prefetched tile to smem (transposed: [k][p], [k][c]).
        #pragma unroll
        for (int it = 0; it < 4; ++it) {
            As[it * 4 + 0][tid] = pa[it].x;
            As[it * 4 + 1][tid] = pa[it].y;
            As[it * 4 + 2][tid] = pa[it].z;
            As[it * 4 + 3][tid] = pa[it].w;
        }
        {
            const int c = tid & 63, kq = tid >> 6;
            Bs[kq * 4 + 0][c] = pb.x;
            Bs[kq * 4 + 1][c] = pb.y;
            Bs[kq * 4 + 2][c] = pb.z;
            Bs[kq * 4 + 3][c] = pb.w;
        }
        __syncthreads();

        // Prefetch next k-tile (overlaps with compute below).
        if (kt + TILE_K < D_) {
            #pragma unroll
            for (int it = 0; it < 4; ++it)
                pa[it] = *(const float4*)(aRow + kt + TILE_K + it * 4);
            pb = *(const float4*)(bRow + kt + TILE_K);
        }

        #pragma unroll
        for (int k = 0; k < TILE_K; ++k) {
            // a: 8 consecutive p values = 4 ready-packed f32x2 operands.
            ulonglong2 a01 = *(const ulonglong2*)&As[k][ty * 8];
            ulonglong2 a23 = *(const ulonglong2*)&As[k][ty * 8 + 4];
            float4 b0 = *(const float4*)&Bs[k][tx * 8];
            float4 b1 = *(const float4*)&Bs[k][tx * 8 + 4];
            unsigned long long av[4] = {a01.x, a01.y, a23.x, a23.y};
            float bv[8] = {b0.x, b0.y, b0.z, b0.w, b1.x, b1.y, b1.z, b1.w};
            #pragma unroll
            for (int j = 0; j < 8; ++j) {
                unsigned long long bb = pack2(bv[j], bv[j]);
                #pragma unroll
                for (int i = 0; i < 4; ++i) fma2(acc[i][j], av[i], bb);
            }
        }
        __syncthreads();
    }

    // Per-thread max over its 8 p rows for each of its 8 c columns.
    #pragma unroll
    for (int j = 0; j < 8; ++j) {
        float m = -3.4e38f;
        #pragma unroll
        for (int i = 0; i < 4; ++i) {
            float x, y;
            unpack2(acc[i][j], x, y);
            m = fmaxf(m, fmaxf(x, y));
        }
        red[ty][tx * 8 + j] = m;
    }
    __syncthreads();
    if (tid < B_) {
        float m = -3.4e38f;
        #pragma unroll
        for (int t = 0; t < 32; ++t) m = fmaxf(m, red[t][tid]);
        g_partial[((size_t)b * NTILES + pt) * B_ + tid] = m;
    }
}

// Single CTA: reduce p-tiles -> simMax[64][64], then bidirectional hinge loss.
__global__ void loss_kernel(const void* __restrict__ lblRaw, float* __restrict__ out) {
    __shared__ float sm[B_][B_ + 1];
    __shared__ int lab[B_];
    __shared__ float r1[256], r2[256], rn[256];
    const int tid = threadIdx.x;

    for (int e = tid; e < B_ * B_; e += 256) {
        const int i = e >> 6, j = e & 63;
        float m = -3.4e38f;
        #pragma unroll
        for (int t = 0; t < NTILES; ++t)
            m = fmaxf(m, g_partial[((size_t)i * NTILES + t) * B_ + j]);
        sm[i][j] = m;
    }

    // Labels: runtime-detect int64 vs int32 storage (values are all in [0,64),
    // so an int64 buffer has zero odd int32 halves; (1/64)^32 false-positive).
    if (tid == 0) {
        const int* l32 = (const int*)lblRaw;
        bool is64 = true;
        for (int i = 0; i < 32; ++i)
            if (l32[2 * i + 1] != 0) { is64 = false; break; }
        if (is64) {
            const long long* l64 = (const long long*)lblRaw;
            for (int i = 0; i < B_; ++i) lab[i] = (int)l64[i];
        } else {
            for (int i = 0; i < B_; ++i) lab[i] = l32[i];
        }
    }
    __syncthreads();

    float s1 = 0.f, s2 = 0.f, n = 0.f;
    for (int e = tid; e < B_ * B_; e += 256) {
        const int i = e >> 6, j = e & 63;
        if (lab[i] != lab[j]) {
            n += 1.f;
            const float p = sm[i][i];
            s1 += fmaxf(sm[i][j] - p + 0.1f, 0.f);   // image -> text
            s2 += fmaxf(sm[j][i] - p + 0.1f, 0.f);   // text -> image
        }
    }
    r1[tid] = s1; r2[tid] = s2; rn[tid] = n;
    __syncthreads();
    for (int s = 128; s > 0; s >>= 1) {
        if (tid < s) {
            r1[tid] += r1[tid + s];
            r2[tid] += r2[tid + s];
            rn[tid] += rn[tid + s];
        }
        __syncthreads();
    }
    if (tid == 0) out[0] = (r1[0] + r2[0]) / (rn[0] + 1e-6f);
}

extern "C" void kernel_launch(void* const* d_in, const int* in_sizes, int n_in,
                              void* d_out, int out_size) {
    (void)in_sizes; (void)n_in; (void)out_size;
    const float* im  = (const float*)d_in[0];   // imFtr  [64, 2048, 1024] f32
    const float* dis = (const float*)d_in[1];   // disFtr [64, 1024] f32
    const void*  lbl = d_in[2];                 // lblList [64] int32 or int64

    dim3 grid(NTILES, B_);
    gemm_max_kernel<<<grid, 256>>>(im, dis);
    loss_kernel<<<1, 256>>>(lbl, (float*)d_out);
}

// round 3
// speedup vs baseline: 2.6841x; 2.6841x over previous
#include <cuda_runtime.h>
#include <cstdint>

#define B_  64
#define P_  2048
#define D_  1024
#define TILE_M 128
#define KC 32
#define NSTAGE (D_ / KC)          /* 32 stages */
#define APITCH 160                /* bytes per A row: 16 pairs*8B + 32 pad */
#define BPITCH 160
#define SMEM_B_OFF (TILE_M * APITCH)              /* 20480 */
#define SMEM_BYTES (SMEM_B_OFF + B_ * BPITCH)     /* 30720 */
#define SMEM_TOTAL 33792                          /* max(stage, 128*66*4 epilogue) */

/* simMax as order-preserving uint keys; zero == encoded -inf sentinel.
   loss_kernel resets to 0 after use so graph replays stay correct. */
__device__ unsigned int g_key[B_ * B_];

__device__ __forceinline__ uint32_t smem_u32(const void* p) {
    uint32_t a;
    asm("{ .reg .u64 t; cvta.to.shared.u64 t, %1; cvt.u32.u64 %0, t; }" : "=r"(a) : "l"(p));
    return a;
}
__device__ __forceinline__ uint32_t pack_bf16x2(float lo_elem, float hi_elem) {
    uint32_t h;  /* low 16 bits <- lo_elem (even k), high <- hi_elem (odd k) */
    asm("cvt.rn.bf16x2.f32 %0, %1, %2;" : "=r"(h) : "f"(hi_elem), "f"(lo_elem));
    return h;
}
/* float4 -> {hi pair, lo pair, hi pair, lo pair} interleaved STS.128 */
__device__ __forceinline__ void cvt_sts(uint32_t addr, float4 v) {
    uint32_t h0 = pack_bf16x2(v.x, v.y);
    float r0 = v.x - __uint_as_float(h0 << 16);
    float r1 = v.y - __uint_as_float(h0 & 0xFFFF0000u);
    uint32_t l0 = pack_bf16x2(r0, r1);
    uint32_t h1 = pack_bf16x2(v.z, v.w);
    float r2 = v.z - __uint_as_float(h1 << 16);
    float r3 = v.w - __uint_as_float(h1 & 0xFFFF0000u);
    uint32_t l1 = pack_bf16x2(r2, r3);
    asm volatile("st.shared.v4.b32 [%0], {%1,%2,%3,%4};"
                 :: "r"(addr), "r"(h0), "r"(l0), "r"(h1), "r"(l1) : "memory");
}
__device__ __forceinline__ void lds64(uint32_t &h, uint32_t &l, uint32_t addr) {
    asm volatile("ld.shared.v2.b32 {%0,%1}, [%2];" : "=r"(h), "=r"(l) : "r"(addr));
}
__device__ __forceinline__ void mma16816(float* c, const uint32_t* a, const uint32_t* b) {
    asm volatile(
        "mma.sync.aligned.m16n8k16.row.col.f32.bf16.bf16.f32 "
        "{%0,%1,%2,%3}, {%4,%5,%6,%7}, {%8,%9}, {%0,%1,%2,%3};"
        : "+f"(c[0]), "+f"(c[1]), "+f"(c[2]), "+f"(c[3])
        : "r"(a[0]), "r"(a[1]), "r"(a[2]), "r"(a[3]), "r"(b[0]), "r"(b[1]));
}

/* Grid (16, 64), 256 threads. CTA: sim[128p x 64c] via split-bf16 HMMA,
   fp32-accurate; per-column max -> atomicMax into g_key. */
__global__ __launch_bounds__(256, 2)
void gemm_max_kernel(const float* __restrict__ im, const float* __restrict__ dis) {
    __shared__ __align__(16) char smem[SMEM_TOTAL];
    const uint32_t sb = smem_u32(smem);
    const int tid = threadIdx.x, lid = tid & 31, wid = tid >> 5;
    const int g = lid >> 2, t = lid & 3;
    const int wm = wid & 3, wn = wid >> 2;
    const int b = blockIdx.y, pt = blockIdx.x;

    /* coalesced gmem mapping: 8 lanes cover one 128B row-chunk */
    const float* aP = im + ((size_t)(b * P_ + pt * TILE_M) + (tid >> 3)) * D_ + (tid & 7) * 4;
    const float* bP = dis + (size_t)(tid >> 2) * D_ + (tid & 3) * 8;
    const uint32_t aSt = sb + (tid >> 3) * APITCH + (tid & 7) * 16;
    const uint32_t bSt = sb + SMEM_B_OFF + (tid >> 2) * BPITCH + (tid & 3) * 32;

    /* fragment base addresses (per-thread) */
    const uint32_t aF = sb + (wm * 32 + g) * APITCH + t * 8;
    const uint32_t bF = sb + SMEM_B_OFF + (wn * 32 + g) * BPITCH + t * 8;

    float acc[2][4][4];
    #pragma unroll
    for (int i = 0; i < 2; ++i)
        #pragma unroll
        for (int j = 0; j < 4; ++j)
            #pragma unroll
            for (int k = 0; k < 4; ++k) acc[i][j][k] = 0.f;

    float4 va[4], vb[2];
    #pragma unroll
    for (int i = 0; i < 4; ++i) va[i] = *(const float4*)(aP + i * 32 * D_);
    vb[0] = *(const float4*)(bP);
    vb[1] = *(const float4*)(bP + 4);

    for (int kt = 0; kt < NSTAGE; ++kt) {
        __syncthreads();   /* previous compute done -> buffer reusable */
        #pragma unroll
        for (int i = 0; i < 4; ++i) cvt_sts(aSt + i * 32 * APITCH, va[i]);
        cvt_sts(bSt, vb[0]);
        cvt_sts(bSt + 16, vb[1]);
        if (kt + 1 < NSTAGE) {   /* prefetch next stage; latency hidden by compute */
            const float* a2 = aP + (kt + 1) * KC;
            #pragma unroll
            for (int i = 0; i < 4; ++i) va[i] = *(const float4*)(a2 + i * 32 * D_);
            vb[0] = *(const float4*)(bP + (kt + 1) * KC);
            vb[1] = *(const float4*)(bP + (kt + 1) * KC + 4);
        }
        __syncthreads();   /* stores visible */

        #pragma unroll
        for (int sub = 0; sub < 2; ++sub) {      /* two k16 chunks per stage */
            uint32_t Bh[4][2], Bl[4][2];
            #pragma unroll
            for (int nt = 0; nt < 4; ++nt) {
                const uint32_t base = bF + nt * 8 * BPITCH + sub * 64;
                lds64(Bh[nt][0], Bl[nt][0], base);
                lds64(Bh[nt][1], Bl[nt][1], base + 32);
            }
            #pragma unroll
            for (int mt = 0; mt < 2; ++mt) {
                uint32_t Ah[4], Al[4];
                const uint32_t base = aF + mt * 16 * APITCH + sub * 64;
                lds64(Ah[0], Al[0], base);
                lds64(Ah[1], Al[1], base + 8 * APITCH);
                lds64(Ah[2], Al[2], base + 32);
                lds64(Ah[3], Al[3], base + 8 * APITCH + 32);
                #pragma unroll
                for (int nt = 0; nt < 4; ++nt) {
                    mma16816(acc[mt][nt], Ah, Bh[nt]);   /* hi*hi */
                    mma16816(acc[mt][nt], Ah, Bl[nt]);   /* hi*lo */
                    mma16816(acc[mt][nt], Al, Bh[nt]);   /* lo*hi */
                }
            }
        }
    }

    /* epilogue: C frags -> smem -> per-column max -> global atomicMax */
    __syncthreads();
    float* red = (float*)smem;   /* [128][66] */
    #pragma unroll
    for (int mt = 0; mt < 2; ++mt) {
        const int r0 = wm * 32 + mt * 16 + g;
        #pragma unroll
        for (int nt = 0; nt < 4; ++nt) {
            const int c = wn * 32 + nt * 8 + t * 2;
            red[r0 * 66 + c]           = acc[mt][nt][0];
            red[r0 * 66 + c + 1]       = acc[mt][nt][1];
            red[(r0 + 8) * 66 + c]     = acc[mt][nt][2];
            red[(r0 + 8) * 66 + c + 1] = acc[mt][nt][3];
        }
    }
    __syncthreads();
    if (tid < 64) {
        float m = -3.4e38f;
        #pragma unroll 8
        for (int r = 0; r < TILE_M; ++r) m = fmaxf(m, red[r * 66 + tid]);
        unsigned int k = __float_as_uint(m);
        k = (k & 0x80000000u) ? ~k : (k | 0x80000000u);
        atomicMax(&g_key[b * B_ + tid], k);
    }
}

/* decode simMax, bidirectional hinge loss, reset g_key for next replay */
__global__ void loss_kernel(const void* __restrict__ lblRaw, float* __restrict__ out) {
    __shared__ float sm[B_][B_ + 1];
    __shared__ int lab[B_];
    __shared__ float rr[3][8];
    const int tid = threadIdx.x;

    for (int e = tid; e < B_ * B_; e += 256) {
        const unsigned int u = g_key[e];
        sm[e >> 6][e & 63] = __uint_as_float((u & 0x80000000u) ? (u ^ 0x80000000u) : ~u);
    }
    if (tid == 0) {
        /* labels in [0,64): an int64 buffer has all-zero odd int32 halves */
        const int* l32 = (const int*)lblRaw;
        bool is64 = true;
        for (int i = 0; i < 32; ++i)
            if (l32[2 * i + 1] != 0) { is64 = false; break; }
        if (is64) {
            const long long* l64 = (const long long*)lblRaw;
            for (int i = 0; i < B_; ++i) lab[i] = (int)l64[i];
        } else {
            for (int i = 0; i < B_; ++i) lab[i] = l32[i];
        }
    }
    __syncthreads();
    for (int e = tid; e < B_ * B_; e += 256) g_key[e] = 0u;  /* reset for next call */

    float s1 = 0.f, s2 = 0.f, n = 0.f;
    for (int e = tid; e < B_ * B_; e += 256) {
        const int i = e >> 6, j = e & 63;
        if (lab[i] != lab[j]) {
            n += 1.f;
            const float p = sm[i][i];
            s1 += fmaxf(sm[i][j] - p + 0.1f, 0.f);
            s2 += fmaxf(sm[j][i] - p + 0.1f, 0.f);
        }
    }
    #pragma unroll
    for (int o = 16; o > 0; o >>= 1) {
        s1 += __shfl_down_sync(0xFFFFFFFFu, s1, o);
        s2 += __shfl_down_sync(0xFFFFFFFFu, s2, o);
        n  += __shfl_down_sync(0xFFFFFFFFu, n,  o);
    }
    if ((tid & 31) == 0) { rr[0][tid >> 5] = s1; rr[1][tid >> 5] = s2; rr[2][tid >> 5] = n; }
    __syncthreads();
    if (tid == 0) {
        float a = 0.f, c = 0.f, d = 0.f;
        #pragma unroll
        for (int w = 0; w < 8; ++w) { a += rr[0][w]; c += rr[1][w]; d += rr[2][w]; }
        out[0] = (a + c) / (d + 1e-6f);
    }
}

extern "C" void kernel_launch(void* const* d_in, const int* in_sizes, int n_in,
                              void* d_out, int out_size) {
    (void)in_sizes; (void)n_in; (void)out_size;
    const float* im  = (const float*)d_in[0];
    const float* dis = (const float*)d_in[1];
    const void*  lbl = d_in[2];

    dim3 grid(P_ / TILE_M, B_);
    gemm_max_kernel<<<grid, 256>>>(im, dis);
    loss_kernel<<<1, 256>>>(lbl, (float*)d_out);
}